// round 1
// baseline (speedup 1.0000x reference)
#include <cuda_runtime.h>

// Problem constants (fixed by the dataset: node_idx=28, P=320, D=3, sigma=10)
#define NNODE 28
#define PPT   320
#define NPTS  (NNODE * PPT)   // 8960 points per tensor
#define MID   13               // (node_idx-2)/2
#define SIGMA 10.0f

// Scratch (no allocations allowed -> device globals)
__device__ float4 g_pts[2][NPTS];            // [0]=clipped X, [1]=clipped T ; w = |p|^2/2
__device__ float  g_M[2][NPTS * NNODE];      // [0]=M_xt[pt][t_node], [1]=M_tx[pt][x_node]
__device__ float  g_part[2 * NPTS / PPT];    // 56 block partials

// ---------------------------------------------------------------------------
// Kernel 1: clip to [-sigma, sigma], pack as float4 (x,y,z, |p|^2/2)
// ---------------------------------------------------------------------------
__global__ void clip_pack_kernel(const float* __restrict__ X,
                                 const float* __restrict__ T) {
    int i = blockIdx.x * blockDim.x + threadIdx.x;
    if (i >= 2 * NPTS) return;
    int sel = (i >= NPTS) ? 1 : 0;
    int p = i - sel * NPTS;
    const float* src = sel ? T : X;
    float x = src[3 * p + 0];
    float y = src[3 * p + 1];
    float z = src[3 * p + 2];
    x = fminf(fmaxf(x, -SIGMA), SIGMA);
    y = fminf(fmaxf(y, -SIGMA), SIGMA);
    z = fminf(fmaxf(z, -SIGMA), SIGMA);
    float w = 0.5f * (x * x + y * y + z * z);
    g_pts[sel][p] = make_float4(x, y, z, w);
}

// ---------------------------------------------------------------------------
// Kernel 2: per-point per-node min squared distance.
// Grid (28, 28, 2). dir=0: rows are X points, cols are T node blockIdx.y.
//                   dir=1: rows are T points, cols are X node blockIdx.y.
// Block (bx, by): thread t owns point bx*320+t of A, scans node by of B (smem),
// writes M[dir][pt*28 + by] — each output cell written by exactly one block.
// Math: d = |a|^2 + |b|^2 - 2 a.b = 2*( a.w + (b.w - a.b) ); minimize f = b.w - a.b
// with negated a -> 3 FFMA per pair.
// ---------------------------------------------------------------------------
__global__ __launch_bounds__(PPT) void pair_min_kernel() {
    const int dir = blockIdx.z;
    const float4* __restrict__ A = g_pts[dir];
    const float4* __restrict__ B = g_pts[dir ^ 1];

    __shared__ float4 sB[PPT];
    const int t = threadIdx.x;
    sB[t] = B[blockIdx.y * PPT + t];
    __syncthreads();

    float4 a = A[blockIdx.x * PPT + t];
    const float ax = -a.x, ay = -a.y, az = -a.z;

    float m0 = 3.0e38f, m1 = 3.0e38f, m2 = 3.0e38f, m3 = 3.0e38f;
#pragma unroll 4
    for (int q = 0; q < PPT; q += 4) {
        float4 b0 = sB[q + 0];
        float4 b1 = sB[q + 1];
        float4 b2 = sB[q + 2];
        float4 b3 = sB[q + 3];
        m0 = fminf(m0, fmaf(ax, b0.x, fmaf(ay, b0.y, fmaf(az, b0.z, b0.w))));
        m1 = fminf(m1, fmaf(ax, b1.x, fmaf(ay, b1.y, fmaf(az, b1.z, b1.w))));
        m2 = fminf(m2, fmaf(ax, b2.x, fmaf(ay, b2.y, fmaf(az, b2.z, b2.w))));
        m3 = fminf(m3, fmaf(ax, b3.x, fmaf(ay, b3.y, fmaf(az, b3.z, b3.w))));
    }
    float m = fminf(fminf(m0, m1), fminf(m2, m3));
    g_M[dir][(blockIdx.x * PPT + t) * NNODE + blockIdx.y] = 2.0f * (m + a.w);
}

// ---------------------------------------------------------------------------
// Kernel 3: per-point closed-form contribution over all 26 subsets + half-arch
// terms, block-reduced (deterministic tree) into g_part.
//
// For point pt in node u with per-node mins v[0..27], full min m at argmin a,
// second min s, v(j) := (a==j ? s : m) = min over nodes != j:
//   sum over subsets idx=0..25 containing u (extra node double-counted):
//     = sum_{idx=0..25} v(idx) - [u<=25]*v(u) + [u<=25]*v(idx_e)
//     = 26*m + (a<=25 ? s-m : 0) + [u<=25]*(v(idx_e) - v(u))
//   plus half-arch term: min over nodes [0,13) if u<13 else [13,28).
// ---------------------------------------------------------------------------
__global__ __launch_bounds__(PPT) void stats_kernel() {
    int gp = blockIdx.x * PPT + threadIdx.x;           // 0 .. 17919
    int dir = (gp >= NPTS) ? 1 : 0;
    int p = gp - dir * NPTS;
    int u = p / PPT;                                   // node of this point
    const float* __restrict__ v = &g_M[dir][p * NNODE];

    float m = 3.0e38f, s = 3.0e38f, h = 3.0e38f;
    int a = -1;
    const int h0 = (u < MID) ? 0 : MID;
    const int h1 = (u < MID) ? MID : NNODE;
#pragma unroll
    for (int j = 0; j < NNODE; j++) {
        float vj = v[j];
        if (vj < m) { s = m; m = vj; a = j; }
        else        { s = fminf(s, vj); }
        if (j >= h0 && j < h1) h = fminf(h, vj);
    }

    float contrib = 26.0f * m + h;
    if (a <= NNODE - 3) contrib += (s - m);            // a in 0..25
    if (u <= NNODE - 3) {                              // u in 0..25
        int idx_e = (u < MID) ? (u + MID) : (u - MID);
        float v_u = (a == u)     ? s : m;
        float v_e = (a == idx_e) ? s : m;
        contrib += v_e - v_u;
    }

    __shared__ float red[PPT];
    red[threadIdx.x] = contrib;
    __syncthreads();
    // 320 -> 256 fold, then power-of-two tree (deterministic)
    if (threadIdx.x < 64) red[threadIdx.x] += red[threadIdx.x + 256];
    __syncthreads();
    for (int off = 128; off > 0; off >>= 1) {
        if (threadIdx.x < off) red[threadIdx.x] += red[threadIdx.x + off];
        __syncthreads();
    }
    if (threadIdx.x == 0) g_part[blockIdx.x] = red[0];
}

// ---------------------------------------------------------------------------
// Kernel 4: deterministic final sum of 56 partials.
// ---------------------------------------------------------------------------
__global__ void final_kernel(float* __restrict__ out) {
    if (threadIdx.x == 0) {
        float ssum = 0.0f;
        for (int i = 0; i < 2 * NPTS / PPT; i++) ssum += g_part[i];
        out[0] = ssum;
    }
}

extern "C" void kernel_launch(void* const* d_in, const int* in_sizes, int n_in,
                              void* d_out, int out_size) {
    const float* X = (const float*)d_in[0];       // X_v        [28,320,3] f32
    const float* T = (const float*)d_in[1];       // target_X_v [28,320,3] f32
    (void)in_sizes; (void)n_in; (void)out_size;   // node_idx fixed at 28

    clip_pack_kernel<<<(2 * NPTS + 255) / 256, 256>>>(X, T);

    dim3 g2(NNODE, NNODE, 2);
    pair_min_kernel<<<g2, PPT>>>();

    stats_kernel<<<2 * NPTS / PPT, PPT>>>();
    final_kernel<<<1, 32>>>((float*)d_out);
}

// round 2
// speedup vs baseline: 1.3951x; 1.3951x over previous
#include <cuda_runtime.h>

// Problem constants (fixed by the dataset: node_idx=28, P=320, D=3, sigma=10)
#define NNODE 28
#define PPT   320
#define NPTS  (NNODE * PPT)   // 8960 points per tensor
#define MID   13              // (node_idx-2)/2
#define SIGMA 10.0f

typedef unsigned long long u64;

// Scratch (no allocations allowed -> device globals)
__device__ float g_M[2][NPTS * NNODE];     // [0]=M_xt[pt][t_node], [1]=M_tx[pt][x_node]
__device__ float g_part[2 * NPTS / PPT];   // 56 block partials

// ---------------------------------------------------------------------------
// Packed f32x2 helpers (Blackwell)
// ---------------------------------------------------------------------------
__device__ __forceinline__ u64 pack2(float lo, float hi) {
    u64 r;
    asm("mov.b64 %0, {%1, %2};" : "=l"(r) : "f"(lo), "f"(hi));
    return r;
}
__device__ __forceinline__ u64 fma2(u64 a, u64 b, u64 c) {
    u64 d;
    asm("fma.rn.f32x2 %0, %1, %2, %3;" : "=l"(d) : "l"(a), "l"(b), "l"(c));
    return d;
}
__device__ __forceinline__ void unpack2(u64 v, float& lo, float& hi) {
    asm("mov.b64 {%0, %1}, %2;" : "=f"(lo), "=f"(hi) : "l"(v));
}
__device__ __forceinline__ float clipf(float v) {
    return fminf(fmaxf(v, -SIGMA), SIGMA);
}

// ---------------------------------------------------------------------------
// Kernel 1: per-point per-node min squared distance (clip fused).
// Grid (28, 28, 2), 160 threads. dir=0: A=X rows vs T node by; dir=1 swapped.
// Thread t owns A points {bx*320+t, bx*320+t+160}; scans B node by from smem.
// Math: d = |a|^2+|b|^2-2 a.b = 2*( a.w + (b.w - a.b) ); minimize f = b.w - a.b
// with negated a. Packed: 2 B points per fma.rn.f32x2 chain.
// SMEM layout: sXY[q] = { pack(x[2q],x[2q+1]), pack(y[2q],y[2q+1]) }
//              sZW[q] = { pack(z[2q],z[2q+1]), pack(w[2q],w[2q+1]) }
// ---------------------------------------------------------------------------
__global__ __launch_bounds__(160) void pair_min_kernel(const float* __restrict__ X,
                                                       const float* __restrict__ T) {
    const int dir = blockIdx.z;
    const float* __restrict__ Araw = dir ? T : X;
    const float* __restrict__ Braw = dir ? X : T;

    __shared__ ulonglong2 sXY[PPT / 2];
    __shared__ ulonglong2 sZW[PPT / 2];

    const int t = threadIdx.x;

    // Fill + clip B node tile (each thread: 2 points)
    {
        const float* bsrc = Braw + (size_t)blockIdx.y * PPT * 3;
        float* fXY = reinterpret_cast<float*>(sXY);
        float* fZW = reinterpret_cast<float*>(sZW);
#pragma unroll
        for (int k = 0; k < 2; k++) {
            int j = t + k * 160;
            float x = clipf(bsrc[3 * j + 0]);
            float y = clipf(bsrc[3 * j + 1]);
            float z = clipf(bsrc[3 * j + 2]);
            float w = fmaf(0.5f * x, x, fmaf(0.5f * y, y, 0.5f * z * z));
            int q = j >> 1, r = j & 1;
            fXY[q * 4 + 0 + r] = x;
            fXY[q * 4 + 2 + r] = y;
            fZW[q * 4 + 0 + r] = z;
            fZW[q * 4 + 2 + r] = w;
        }
    }
    __syncthreads();

    // Load + clip 2 A points
    const float* asrc = Araw + (size_t)blockIdx.x * PPT * 3;
    float a0x = clipf(asrc[3 * t + 0]);
    float a0y = clipf(asrc[3 * t + 1]);
    float a0z = clipf(asrc[3 * t + 2]);
    float a1x = clipf(asrc[3 * (t + 160) + 0]);
    float a1y = clipf(asrc[3 * (t + 160) + 1]);
    float a1z = clipf(asrc[3 * (t + 160) + 2]);
    float a0w = fmaf(0.5f * a0x, a0x, fmaf(0.5f * a0y, a0y, 0.5f * a0z * a0z));
    float a1w = fmaf(0.5f * a1x, a1x, fmaf(0.5f * a1y, a1y, 0.5f * a1z * a1z));

    const u64 nax0 = pack2(-a0x, -a0x), nay0 = pack2(-a0y, -a0y), naz0 = pack2(-a0z, -a0z);
    const u64 nax1 = pack2(-a1x, -a1x), nay1 = pack2(-a1y, -a1y), naz1 = pack2(-a1z, -a1z);

    float m0a = 3.0e38f, m0b = 3.0e38f, m1a = 3.0e38f, m1b = 3.0e38f;

#pragma unroll 4
    for (int q = 0; q < PPT / 2; q++) {
        ulonglong2 bxy = sXY[q];   // .x = packed x pair, .y = packed y pair
        ulonglong2 bzw = sZW[q];   // .x = packed z pair, .y = packed w pair

        u64 t0 = fma2(naz0, bzw.x, bzw.y);
        t0 = fma2(nay0, bxy.y, t0);
        t0 = fma2(nax0, bxy.x, t0);
        float lo, hi;
        unpack2(t0, lo, hi);
        m0a = fminf(m0a, lo);
        m0b = fminf(m0b, hi);

        u64 t1 = fma2(naz1, bzw.x, bzw.y);
        t1 = fma2(nay1, bxy.y, t1);
        t1 = fma2(nax1, bxy.x, t1);
        unpack2(t1, lo, hi);
        m1a = fminf(m1a, lo);
        m1b = fminf(m1b, hi);
    }

    float m0 = fminf(m0a, m0b);
    float m1 = fminf(m1a, m1b);
    float* __restrict__ M = g_M[dir];
    M[((size_t)blockIdx.x * PPT + t) * NNODE + blockIdx.y] = 2.0f * (m0 + a0w);
    M[((size_t)blockIdx.x * PPT + t + 160) * NNODE + blockIdx.y] = 2.0f * (m1 + a1w);
}

// ---------------------------------------------------------------------------
// Kernel 2: per-point closed-form contribution over all 26 subsets + half-arch
// terms, block-reduced (deterministic tree) into g_part.
//
// For point pt in node u with per-node mins v[0..27], full min m at argmin a,
// second min s, v(j) := (a==j ? s : m) = min over nodes != j:
//   contrib = 26*m + (a<=25 ? s-m : 0) + [u<=25]*(v(idx_e) - v(u)) + halfmin
// ---------------------------------------------------------------------------
__global__ __launch_bounds__(PPT) void stats_kernel() {
    int gp = blockIdx.x * PPT + threadIdx.x;           // 0 .. 17919
    int dir = (gp >= NPTS) ? 1 : 0;
    int p = gp - dir * NPTS;
    int u = p / PPT;                                   // node of this point
    const float* __restrict__ v = &g_M[dir][(size_t)p * NNODE];

    float m = 3.0e38f, s = 3.0e38f, h = 3.0e38f;
    int a = -1;
    const int h0 = (u < MID) ? 0 : MID;
    const int h1 = (u < MID) ? MID : NNODE;
#pragma unroll
    for (int j = 0; j < NNODE; j++) {
        float vj = v[j];
        if (vj < m) { s = m; m = vj; a = j; }
        else        { s = fminf(s, vj); }
        if (j >= h0 && j < h1) h = fminf(h, vj);
    }

    float contrib = 26.0f * m + h;
    if (a <= NNODE - 3) contrib += (s - m);            // a in 0..25
    if (u <= NNODE - 3) {                              // u in 0..25
        int idx_e = (u < MID) ? (u + MID) : (u - MID);
        float v_u = (a == u)     ? s : m;
        float v_e = (a == idx_e) ? s : m;
        contrib += v_e - v_u;
    }

    __shared__ float red[PPT];
    red[threadIdx.x] = contrib;
    __syncthreads();
    if (threadIdx.x < 64) red[threadIdx.x] += red[threadIdx.x + 256];
    __syncthreads();
    for (int off = 128; off > 0; off >>= 1) {
        if (threadIdx.x < off) red[threadIdx.x] += red[threadIdx.x + off];
        __syncthreads();
    }
    if (threadIdx.x == 0) g_part[blockIdx.x] = red[0];
}

// ---------------------------------------------------------------------------
// Kernel 3: deterministic parallel final sum of 56 partials.
// ---------------------------------------------------------------------------
__global__ void final_kernel(float* __restrict__ out) {
    __shared__ float red[64];
    int t = threadIdx.x;
    red[t] = (t < 2 * NPTS / PPT) ? g_part[t] : 0.0f;
    __syncthreads();
#pragma unroll
    for (int off = 32; off > 0; off >>= 1) {
        if (t < off) red[t] += red[t + off];
        __syncthreads();
    }
    if (t == 0) out[0] = red[0];
}

extern "C" void kernel_launch(void* const* d_in, const int* in_sizes, int n_in,
                              void* d_out, int out_size) {
    const float* X = (const float*)d_in[0];       // X_v        [28,320,3] f32
    const float* T = (const float*)d_in[1];       // target_X_v [28,320,3] f32
    (void)in_sizes; (void)n_in; (void)out_size;   // node_idx fixed at 28

    dim3 g1(NNODE, NNODE, 2);
    pair_min_kernel<<<g1, 160>>>(X, T);

    stats_kernel<<<2 * NPTS / PPT, PPT>>>();
    final_kernel<<<1, 64>>>((float*)d_out);
}

// round 4
// speedup vs baseline: 1.4233x; 1.0202x over previous
#include <cuda_runtime.h>

// Problem constants (fixed by the dataset: node_idx=28, P=320, D=3, sigma=10)
#define NNODE 28
#define PPT   320
#define NPTS  (NNODE * PPT)   // 8960 points per tensor
#define MID   13              // (node_idx-2)/2
#define SIGMA 10.0f

#define STATS_THREADS 256
#define STATS_BLOCKS  (2 * NPTS / STATS_THREADS)   // 70

typedef unsigned long long u64;

// Scratch (no allocations allowed -> device globals)
// Transposed layout: g_M[dir][node * NPTS + pt]  (coalesced stores AND loads)
__device__ float g_M[2][NNODE * NPTS];
__device__ float g_part[STATS_BLOCKS];

// ---------------------------------------------------------------------------
// Packed f32x2 helpers (Blackwell sm_100+). NOTE: no packed min exists; the
// mov.b64 unpack maps to register-pair halves and is elided by ptxas.
// ---------------------------------------------------------------------------
__device__ __forceinline__ u64 pack2(float lo, float hi) {
    u64 r;
    asm("mov.b64 %0, {%1, %2};" : "=l"(r) : "f"(lo), "f"(hi));
    return r;
}
__device__ __forceinline__ u64 fma2(u64 a, u64 b, u64 c) {
    u64 d;
    asm("fma.rn.f32x2 %0, %1, %2, %3;" : "=l"(d) : "l"(a), "l"(b), "l"(c));
    return d;
}
__device__ __forceinline__ void unpack2(u64 v, float& lo, float& hi) {
    asm("mov.b64 {%0, %1}, %2;" : "=f"(lo), "=f"(hi) : "l"(v));
}
__device__ __forceinline__ float clipf(float v) {
    return fminf(fmaxf(v, -SIGMA), SIGMA);
}

// ---------------------------------------------------------------------------
// Kernel 1: per-point per-node min squared distance (clip fused).
// Grid (14, 28, 2), 160 threads. dir selects A/B role; blockIdx.x covers TWO
// A nodes (4 A points per thread), blockIdx.y one B node (tile in smem).
// Math: d = |a|^2+|b|^2-2 a.b = 2*( a.w + (b.w - a.b) ); minimize f = b.w - a.b
// with negated a. Packed: 2 B points per fma.rn.f32x2 chain; scalar FMNMX on
// the two register-pair halves accumulates the min.
// SMEM layout: sXY[q] = { pack(x[2q],x[2q+1]), pack(y[2q],y[2q+1]) }
//              sZW[q] = { pack(z[2q],z[2q+1]), pack(w[2q],w[2q+1]) }
// ---------------------------------------------------------------------------
__global__ __launch_bounds__(160) void pair_min_kernel(const float* __restrict__ X,
                                                       const float* __restrict__ T) {
    const int dir = blockIdx.z;
    const float* __restrict__ Araw = dir ? T : X;
    const float* __restrict__ Braw = dir ? X : T;

    __shared__ ulonglong2 sXY[PPT / 2];
    __shared__ ulonglong2 sZW[PPT / 2];

    const int t = threadIdx.x;

    // Fill + clip B node tile (each thread: 2 points)
    {
        const float* bsrc = Braw + (size_t)blockIdx.y * PPT * 3;
        float* fXY = reinterpret_cast<float*>(sXY);
        float* fZW = reinterpret_cast<float*>(sZW);
#pragma unroll
        for (int k = 0; k < 2; k++) {
            int j = t + k * 160;
            float x = clipf(bsrc[3 * j + 0]);
            float y = clipf(bsrc[3 * j + 1]);
            float z = clipf(bsrc[3 * j + 2]);
            float w = fmaf(0.5f * x, x, fmaf(0.5f * y, y, 0.5f * z * z));
            int q = j >> 1, r = j & 1;
            fXY[q * 4 + 0 + r] = x;
            fXY[q * 4 + 2 + r] = y;
            fZW[q * 4 + 0 + r] = z;
            fZW[q * 4 + 2 + r] = w;
        }
    }
    __syncthreads();

    // Load + clip 4 A points (2 nodes' worth: base point = blockIdx.x*640)
    const int aBase = blockIdx.x * (2 * PPT);
    const float* asrc = Araw + (size_t)aBase * 3;
    u64 nax[4], nay[4], naz[4];
    float aw[4];
#pragma unroll
    for (int k = 0; k < 4; k++) {
        int j = t + k * 160;
        float x = clipf(asrc[3 * j + 0]);
        float y = clipf(asrc[3 * j + 1]);
        float z = clipf(asrc[3 * j + 2]);
        aw[k] = fmaf(0.5f * x, x, fmaf(0.5f * y, y, 0.5f * z * z));
        nax[k] = pack2(-x, -x);
        nay[k] = pack2(-y, -y);
        naz[k] = pack2(-z, -z);
    }

    float mlo[4], mhi[4];
#pragma unroll
    for (int k = 0; k < 4; k++) { mlo[k] = 3.0e38f; mhi[k] = 3.0e38f; }

#pragma unroll 4
    for (int q = 0; q < PPT / 2; q++) {
        ulonglong2 bxy = sXY[q];   // .x = packed x pair, .y = packed y pair
        ulonglong2 bzw = sZW[q];   // .x = packed z pair, .y = packed w pair
#pragma unroll
        for (int k = 0; k < 4; k++) {
            u64 f = fma2(naz[k], bzw.x, bzw.y);
            f = fma2(nay[k], bxy.y, f);
            f = fma2(nax[k], bxy.x, f);
            float lo, hi;
            unpack2(f, lo, hi);        // register-pair alias: no SASS cost
            mlo[k] = fminf(mlo[k], lo);
            mhi[k] = fminf(mhi[k], hi);
        }
    }

    // Epilogue: finish, coalesced store into transposed M
    float* __restrict__ Mrow = g_M[dir] + (size_t)blockIdx.y * NPTS + aBase;
#pragma unroll
    for (int k = 0; k < 4; k++) {
        Mrow[t + k * 160] = 2.0f * (fminf(mlo[k], mhi[k]) + aw[k]);
    }
}

// ---------------------------------------------------------------------------
// Kernel 2: per-point closed-form contribution over all 26 subsets + half-arch
// terms, block-reduced (deterministic tree) into g_part.
//
// For point pt in node u with per-node mins v[0..27], full min m at argmin a,
// second min s, v(j) := (a==j ? s : m) = min over nodes != j:
//   contrib = 26*m + (a<=25 ? s-m : 0) + [u<=25]*(v(idx_e) - v(u)) + halfmin
// ---------------------------------------------------------------------------
__global__ __launch_bounds__(STATS_THREADS) void stats_kernel() {
    int gp = blockIdx.x * STATS_THREADS + threadIdx.x;   // 0 .. 17919
    int dir = (gp >= NPTS) ? 1 : 0;
    int p = gp - dir * NPTS;
    int u = p / PPT;                                     // node of this point
    const float* __restrict__ Md = g_M[dir];

    float m = 3.0e38f, s = 3.0e38f, h = 3.0e38f;
    int a = -1;
    const int h0 = (u < MID) ? 0 : MID;
    const int h1 = (u < MID) ? MID : NNODE;
#pragma unroll
    for (int j = 0; j < NNODE; j++) {
        float vj = Md[(size_t)j * NPTS + p];             // coalesced across warp
        if (vj < m) { s = m; m = vj; a = j; }
        else        { s = fminf(s, vj); }
        if (j >= h0 && j < h1) h = fminf(h, vj);
    }

    float contrib = 26.0f * m + h;
    if (a <= NNODE - 3) contrib += (s - m);              // a in 0..25
    if (u <= NNODE - 3) {                                // u in 0..25
        int idx_e = (u < MID) ? (u + MID) : (u - MID);
        float v_u = (a == u)     ? s : m;
        float v_e = (a == idx_e) ? s : m;
        contrib += v_e - v_u;
    }

    __shared__ float red[STATS_THREADS];
    red[threadIdx.x] = contrib;
    __syncthreads();
#pragma unroll
    for (int off = STATS_THREADS / 2; off > 0; off >>= 1) {
        if (threadIdx.x < off) red[threadIdx.x] += red[threadIdx.x + off];
        __syncthreads();
    }
    if (threadIdx.x == 0) g_part[blockIdx.x] = red[0];
}

// ---------------------------------------------------------------------------
// Kernel 3: deterministic parallel final sum of 70 partials.
// ---------------------------------------------------------------------------
__global__ void final_kernel(float* __restrict__ out) {
    __shared__ float red[128];
    int t = threadIdx.x;
    red[t] = (t < STATS_BLOCKS) ? g_part[t] : 0.0f;
    __syncthreads();
#pragma unroll
    for (int off = 64; off > 0; off >>= 1) {
        if (t < off) red[t] += red[t + off];
        __syncthreads();
    }
    if (t == 0) out[0] = red[0];
}

extern "C" void kernel_launch(void* const* d_in, const int* in_sizes, int n_in,
                              void* d_out, int out_size) {
    const float* X = (const float*)d_in[0];       // X_v        [28,320,3] f32
    const float* T = (const float*)d_in[1];       // target_X_v [28,320,3] f32
    (void)in_sizes; (void)n_in; (void)out_size;   // node_idx fixed at 28

    dim3 g1(NNODE / 2, NNODE, 2);
    pair_min_kernel<<<g1, 160>>>(X, T);

    stats_kernel<<<STATS_BLOCKS, STATS_THREADS>>>();
    final_kernel<<<1, 128>>>((float*)d_out);
}

// round 5
// speedup vs baseline: 1.6046x; 1.1273x over previous
#include <cuda_runtime.h>

// Problem constants (fixed by the dataset: node_idx=28, P=320, D=3, sigma=10)
#define NNODE 28
#define PPT   320
#define NPTS  (NNODE * PPT)   // 8960 points per tensor
#define MID   13              // (node_idx-2)/2
#define SIGMA 10.0f

#define HALF_B   160                     // B half-tile size
#define NHB      (2 * NNODE)             // 56 half-rows
#define STATS_THREADS 512
#define STATS_BLOCKS  (2 * NPTS / STATS_THREADS)   // 35

typedef unsigned long long u64;

// Scratch (no allocations allowed -> device globals)
// g_M[dir][hb * NPTS + pt], hb = 2*node + half : raw f = min(b.w - a.b)
__device__ float g_M[2][NHB * NPTS];       // 4 MB
__device__ float g_aw[2][NPTS];            // per-point |a|^2/2 (clipped)
__device__ float g_part[STATS_BLOCKS];
__device__ int   g_cnt;

// ---------------------------------------------------------------------------
// Packed f32x2 helpers (Blackwell sm_100+). No packed min exists; mov.b64
// unpack maps to register-pair halves and is elided by ptxas.
// ---------------------------------------------------------------------------
__device__ __forceinline__ u64 pack2(float lo, float hi) {
    u64 r;
    asm("mov.b64 %0, {%1, %2};" : "=l"(r) : "f"(lo), "f"(hi));
    return r;
}
__device__ __forceinline__ u64 fma2(u64 a, u64 b, u64 c) {
    u64 d;
    asm("fma.rn.f32x2 %0, %1, %2, %3;" : "=l"(d) : "l"(a), "l"(b), "l"(c));
    return d;
}
__device__ __forceinline__ void unpack2(u64 v, float& lo, float& hi) {
    asm("mov.b64 {%0, %1}, %2;" : "=f"(lo), "=f"(hi) : "l"(v));
}
__device__ __forceinline__ float clipf(float v) {
    return fminf(fmaxf(v, -SIGMA), SIGMA);
}

// ---------------------------------------------------------------------------
// Kernel 1: per-point per-B-half min of f = b.w - a.b  (clip fused).
// Grid (14, 56, 2), 160 threads. blockIdx.x: 2 A nodes (4 A pts/thread),
// blockIdx.y: B half-tile (node = y>>1, half = y&1, 160 pts in smem),
// blockIdx.z: direction. d = 2*(f + a.w); a.w handled in stats (constant
// per point, commutes with all mins). Resets g_cnt for the fused final sum.
// SMEM: sXY[q] = { pack(x2q,x2q+1), pack(y2q,y2q+1) }, sZW likewise z/w.
// ---------------------------------------------------------------------------
__global__ __launch_bounds__(160, 8) void pair_min_kernel(const float* __restrict__ X,
                                                          const float* __restrict__ T) {
    if (blockIdx.x == 0 && blockIdx.y == 0 && blockIdx.z == 0 && threadIdx.x == 0)
        g_cnt = 0;

    const int dir = blockIdx.z;
    const float* __restrict__ Araw = dir ? T : X;
    const float* __restrict__ Braw = dir ? X : T;

    __shared__ ulonglong2 sXY[HALF_B / 2];
    __shared__ ulonglong2 sZW[HALF_B / 2];

    const int t = threadIdx.x;

    // Fill + clip B half-tile (one point per thread)
    {
        const int node = blockIdx.y >> 1, half = blockIdx.y & 1;
        const float* bsrc = Braw + ((size_t)node * PPT + half * HALF_B) * 3;
        float x = clipf(bsrc[3 * t + 0]);
        float y = clipf(bsrc[3 * t + 1]);
        float z = clipf(bsrc[3 * t + 2]);
        float w = fmaf(0.5f * x, x, fmaf(0.5f * y, y, 0.5f * z * z));
        float* fXY = reinterpret_cast<float*>(sXY);
        float* fZW = reinterpret_cast<float*>(sZW);
        int q = t >> 1, r = t & 1;
        fXY[q * 4 + 0 + r] = x;
        fXY[q * 4 + 2 + r] = y;
        fZW[q * 4 + 0 + r] = z;
        fZW[q * 4 + 2 + r] = w;
    }
    __syncthreads();

    // Load + clip 4 A points (2 nodes: base point = blockIdx.x*640)
    const int aBase = blockIdx.x * (2 * PPT);
    const float* asrc = Araw + (size_t)aBase * 3;
    u64 nax[4], nay[4], naz[4];
#pragma unroll
    for (int k = 0; k < 4; k++) {
        int j = t + k * 160;
        float x = clipf(asrc[3 * j + 0]);
        float y = clipf(asrc[3 * j + 1]);
        float z = clipf(asrc[3 * j + 2]);
        nax[k] = pack2(-x, -x);
        nay[k] = pack2(-y, -y);
        naz[k] = pack2(-z, -z);
    }

    float m[4];
#pragma unroll
    for (int k = 0; k < 4; k++) m[k] = 3.0e38f;

#pragma unroll 2
    for (int q = 0; q < HALF_B / 2; q++) {
        ulonglong2 bxy = sXY[q];   // .x = packed x pair, .y = packed y pair
        ulonglong2 bzw = sZW[q];   // .x = packed z pair, .y = packed w pair
#pragma unroll
        for (int k = 0; k < 4; k++) {
            u64 f = fma2(naz[k], bzw.x, bzw.y);
            f = fma2(nay[k], bxy.y, f);
            f = fma2(nax[k], bxy.x, f);
            float lo, hi;
            unpack2(f, lo, hi);              // register-pair alias: no SASS cost
            m[k] = fminf(m[k], fminf(lo, hi));
        }
    }

    // Epilogue: coalesced store of raw f-mins
    float* __restrict__ Mrow = g_M[dir] + (size_t)blockIdx.y * NPTS + aBase;
#pragma unroll
    for (int k = 0; k < 4; k++) Mrow[t + k * 160] = m[k];

    // One block column per (bx, dir) also records a.w per point
    if (blockIdx.y == 0) {
        float* __restrict__ AW = g_aw[dir] + aBase;
#pragma unroll
        for (int k = 0; k < 4; k++) {
            int j = t + k * 160;
            float x = clipf(asrc[3 * j + 0]);
            float y = clipf(asrc[3 * j + 1]);
            float z = clipf(asrc[3 * j + 2]);
            AW[j] = fmaf(0.5f * x, x, fmaf(0.5f * y, y, 0.5f * z * z));
        }
    }
}

// ---------------------------------------------------------------------------
// Kernel 2: per-point closed-form contribution over all 26 subsets + half-arch
// terms (in f-space; aw added once), block-reduced, final sum fused via
// last-block-done (deterministic: fixed-order sums only).
//
// Per point in node u with per-node f-mins v[0..27] (folded from half rows),
// full min m at argmin a, second min s, half-range min h:
//   contrib_f = 26*m + (a<=25 ? s-m : 0) + [u<=25]*(v(e)-v(u)) + h
//   contrib   = 2*(contrib_f + 27*aw)     [27 d-terms; diffs cancel aw]
// ---------------------------------------------------------------------------
__global__ __launch_bounds__(STATS_THREADS) void stats_kernel(float* __restrict__ out) {
    int gp = blockIdx.x * STATS_THREADS + threadIdx.x;   // 0 .. 17919
    int dir = (gp >= NPTS) ? 1 : 0;
    int p = gp - dir * NPTS;
    int u = p / PPT;                                     // node of this point
    const float* __restrict__ Md = g_M[dir];

    float m = 3.0e38f, s = 3.0e38f, h = 3.0e38f;
    int a = -1;
    const int h0 = (u < MID) ? 0 : MID;
    const int h1 = (u < MID) ? MID : NNODE;
#pragma unroll
    for (int j = 0; j < NNODE; j++) {
        float f0 = Md[(size_t)(2 * j + 0) * NPTS + p];   // coalesced
        float f1 = Md[(size_t)(2 * j + 1) * NPTS + p];
        float vj = fminf(f0, f1);
        if (vj < m) { s = m; m = vj; a = j; }
        else        { s = fminf(s, vj); }
        if (j >= h0 && j < h1) h = fminf(h, vj);
    }

    float cf = 26.0f * m + h;
    if (a <= NNODE - 3) cf += (s - m);                   // a in 0..25
    if (u <= NNODE - 3) {                                // u in 0..25
        int idx_e = (u < MID) ? (u + MID) : (u - MID);
        float v_u = (a == u)     ? s : m;
        float v_e = (a == idx_e) ? s : m;
        cf += v_e - v_u;
    }
    float contrib = 2.0f * (cf + 27.0f * g_aw[dir][p]);

    __shared__ float red[STATS_THREADS];
    red[threadIdx.x] = contrib;
    __syncthreads();
#pragma unroll
    for (int off = STATS_THREADS / 2; off > 0; off >>= 1) {
        if (threadIdx.x < off) red[threadIdx.x] += red[threadIdx.x + off];
        __syncthreads();
    }

    if (threadIdx.x == 0) {
        g_part[blockIdx.x] = red[0];
        __threadfence();
        int old = atomicAdd(&g_cnt, 1);
        if (old == STATS_BLOCKS - 1) {                   // last block: all parts visible
            float ssum = 0.0f;
#pragma unroll
            for (int i = 0; i < STATS_BLOCKS; i++) ssum += g_part[i];
            out[0] = ssum;
        }
    }
}

extern "C" void kernel_launch(void* const* d_in, const int* in_sizes, int n_in,
                              void* d_out, int out_size) {
    const float* X = (const float*)d_in[0];       // X_v        [28,320,3] f32
    const float* T = (const float*)d_in[1];       // target_X_v [28,320,3] f32
    (void)in_sizes; (void)n_in; (void)out_size;   // node_idx fixed at 28

    dim3 g1(NNODE / 2, NHB, 2);                   // (14, 56, 2)
    pair_min_kernel<<<g1, 160>>>(X, T);

    stats_kernel<<<STATS_BLOCKS, STATS_THREADS>>>((float*)d_out);
}